// round 17
// baseline (speedup 1.0000x reference)
#include <cuda_runtime.h>
#include <cuda_fp16.h>
#include <cstdint>

// ============================================================================
// AutoEncoder_BNN via mma.sync fp16, fp32 accumulate.
// fp32 GEMMs emulated with fp16 2-term split operands (K'=2K):
//   A=[hi|lo], B=[hi|hi]  ->  (A_hi+A_lo)@B_hi, residual ~1.4e-4 per GEMM
// R5..R16: weight-level Karatsuba, weight composition, plain-fp16 finals,
// 2-term everything, heterogeneous fused launches (runtime GemmArgs).
// R17: G1 reads fp32 x DIRECTLY — the A-loader converts float4 -> hi/lo fp16
//      in-flight (k-tiles [0,K/2) are hi, [K/2,K) are lo; each 64-wide tile
//      is uniform). Bit-identical math, deletes the 256MB xcat pack (~110us).
//      Also: G/Bm/(G+Bm) packs fused into one kernel; W_p/W_q packh merged.
// ============================================================================

// ---------------- device scratch (static; no runtime allocation) ------------
__device__ __half g_whcat[1024L  * 12288];
__device__ __half g_h1cat[8192L  * 3072];
__device__ __half g_wh2cat[1024L * 3072];
__device__ __half g_h2cat[8192L  * 3072];
__device__ __half g_wycat[4096L  * 3072];     // W_y B-side (G3, 2-seg)
__device__ __half g_gacat[2048L  * 6144];     // G    A-side 2-seg
__device__ __half g_bacat[2048L  * 6144];     // Bm   A-side 2-seg
__device__ __half g_gpacat[2048L * 6144];     // G+Bm A-side 2-seg
__device__ __half g_wytcat[3L * 1024 * 6144]; // WyuT | WywT | (Wyu+Wyw)T 2-seg
__device__ float  g_wg   [3L * 2048 * 1024];  // m1 | m2 | m3 (fp32)
__device__ __half g_wreim[4096L * 3072];      // [Wre;Wim] B-side 2-seg
__device__ float  g_breim[4096];              // [bre | bim]
__device__ float  g_t    [8192L * 4096];      // [Re | Im] row-major
__device__ __half g_pph  [8192L * 2048];      // pp plain fp16
__device__ __half g_qph  [8192L * 2048];      // qp plain fp16
__device__ __half g_wph  [2048L * 2048];      // W_p plain fp16
__device__ __half g_wqh  [2048L * 2048];      // W_q plain fp16

// ---------------- PTX helpers ------------------------------------------------
__device__ __forceinline__ uint32_t smem_u32(const void* p) {
    uint32_t a;
    asm("{ .reg .u64 t; cvta.to.shared.u64 t, %1; cvt.u32.u64 %0, t; }" : "=r"(a) : "l"(p));
    return a;
}
__device__ __forceinline__ void cp_async16(uint32_t dst, const void* src) {
    asm volatile("cp.async.cg.shared.global [%0], [%1], 16;" :: "r"(dst), "l"(src) : "memory");
}
__device__ __forceinline__ void cp_commit() {
    asm volatile("cp.async.commit_group;" ::: "memory");
}
__device__ __forceinline__ void cp_wait1() {
    asm volatile("cp.async.wait_group 1;" ::: "memory");
}
__device__ __forceinline__ void sts128(uint32_t addr, uint32_t r0, uint32_t r1,
                                       uint32_t r2, uint32_t r3) {
    asm volatile("st.shared.v4.b32 [%0], {%1,%2,%3,%4};"
                 :: "r"(addr), "r"(r0), "r"(r1), "r"(r2), "r"(r3) : "memory");
}
__device__ __forceinline__ void ldsm4(uint32_t* r, uint32_t addr) {
    asm volatile("ldmatrix.sync.aligned.m8n8.x4.shared.b16 {%0,%1,%2,%3}, [%4];"
                 : "=r"(r[0]), "=r"(r[1]), "=r"(r[2]), "=r"(r[3]) : "r"(addr));
}
__device__ __forceinline__ void mma16816(float* c, const uint32_t* a, uint32_t b0, uint32_t b1) {
    asm volatile(
        "mma.sync.aligned.m16n8k16.row.col.f32.f16.f16.f32 "
        "{%0,%1,%2,%3}, {%4,%5,%6,%7}, {%8,%9}, {%0,%1,%2,%3};"
        : "+f"(c[0]), "+f"(c[1]), "+f"(c[2]), "+f"(c[3])
        : "r"(a[0]), "r"(a[1]), "r"(a[2]), "r"(a[3]), "r"(b0), "r"(b1));
}
__device__ __forceinline__ void split2h(float a, float b, __half2& h, __half2& l) {
    const __half ha = __float2half_rn(a);
    const __half hb = __float2half_rn(b);
    h = __halves2half2(ha, hb);
    l = __halves2half2(__float2half_rn(a - __half2float(ha)),
                       __float2half_rn(b - __half2float(hb)));
}
__device__ __forceinline__ uint32_t hbits(__half2 h) { return *reinterpret_cast<uint32_t*>(&h); }
__device__ __forceinline__ uint32_t hi2(float a, float b) {
    __half2 h = __floats2half2_rn(a, b);
    return hbits(h);
}
__device__ __forceinline__ uint32_t lo2(float a, float b) {
    const __half ha = __float2half_rn(a), hb = __float2half_rn(b);
    __half2 l = __halves2half2(__float2half_rn(a - __half2float(ha)),
                               __float2half_rn(b - __half2float(hb)));
    return hbits(l);
}
__device__ __forceinline__ uint2 pack8h(__half2 a, __half2 b) {
    return make_uint2(hbits(a), hbits(b));
}

// ---------------- mma.sync GEMM, tile 128x128x64, 256 threads ----------------
// Runtime-parameterized heterogeneous z-slices.
// mode 0: fp32 C.  mode 1: fp16 2-seg split [hi|lo] to S, row stride 3*Nfull.
// Afp != nullptr: A is fp32 (row stride lda floats); loader converts in-flight
//   (k-tiles [0,K/2) -> hi, [K/2,K) -> lo).  Bit-identical to packed split.
struct GemmArgs {
    const __half* A;
    const __half* B;
    const float* bias;    // nullptr = no bias
    float* C;
    __half* S;
    const float* Afp;     // fp32 direct A (nullptr = use A)
    int lda, ldb, ldc, Nfull, K;
    int nby;              // valid y-blocks for this slice
    int mode, relu;
};

constexpr int SMEM_BYTES = 3 * 32768;   // 3 stages x (A 16KB + B 16KB)

__global__ __launch_bounds__(256, 2)
void gemm_mma(GemmArgs g0, GemmArgs g1, GemmArgs g2, GemmArgs g3)
{
    const GemmArgs& g = (blockIdx.z == 0) ? g0 : (blockIdx.z == 1) ? g1 :
                        (blockIdx.z == 2) ? g2 : g3;
    if ((int)blockIdx.y >= g.nby) return;
    extern __shared__ __align__(1024) char smem[];
    const uint32_t sb = smem_u32(smem);
    const int tid = threadIdx.x, lane = tid & 31, wid = tid >> 5;
    const int wm = wid & 1, wn = wid >> 1;            // warp grid 2(m) x 4(n)
    const int m0 = blockIdx.y * 128, n0 = blockIdx.x * 128;

    // ---- global->shared loader mapping (16B chunks, SW128 swizzle) ----
    const int lrow = tid >> 3;
    const int lc16 = tid & 7;
    uint32_t ld_off[4];
#pragma unroll
    for (int w2 = 0; w2 < 4; ++w2) {
        const int r = lrow + w2 * 32;
        ld_off[w2] = r * 128 + ((lc16 * 16) ^ ((r & 7) << 4));
    }
    const int lda = g.lda, ldb = g.ldb;
    const __half* Ag = g.A + (size_t)(m0 + lrow) * lda + lc16 * 8;
    const __half* Bg = g.B + (size_t)(n0 + lrow) * ldb + lc16 * 8;
    const float*  Xg = g.Afp ? g.Afp + (size_t)(m0 + lrow) * lda + lc16 * 8 : nullptr;
    const int khalf = g.K >> 1;

    // ---- ldmatrix address precompute ----
    uint32_t aTerm[4], aXor[4];
#pragma unroll
    for (int mt = 0; mt < 4; ++mt) {
        const int r = wm * 64 + mt * 16 + ((lane >> 3) & 1) * 8 + (lane & 7);
        aTerm[mt] = r * 128; aXor[mt] = (r & 7) << 4;
    }
    const uint32_t aCol = (lane >> 4) * 16;
    uint32_t bTerm[2], bXor[2];
#pragma unroll
    for (int nt = 0; nt < 2; ++nt) {
        const int r = wn * 32 + nt * 16 + (lane >> 4) * 8 + (lane & 7);
        bTerm[nt] = r * 128; bXor[nt] = (r & 7) << 4;
    }
    const uint32_t bCol = ((lane >> 3) & 1) * 16;

    float acc[4][4][4];
#pragma unroll
    for (int mt = 0; mt < 4; ++mt)
#pragma unroll
        for (int n8 = 0; n8 < 4; ++n8)
#pragma unroll
            for (int j = 0; j < 4; ++j) acc[mt][n8][j] = 0.0f;

    const int nst = g.K / 64;

    auto issue = [&](int s, int kt) {
        const uint32_t sa = sb + (uint32_t)s * 32768u;
        if (Xg) {   // fp32-direct A with in-flight split (uniform hi/lo per tile)
            const bool lo = kt >= khalf;
            const int kc = lo ? kt - khalf : kt;
#pragma unroll
            for (int w2 = 0; w2 < 4; ++w2) {
                const float* sp = Xg + (size_t)w2 * 32 * lda + kc;
                const float4 v0 = *reinterpret_cast<const float4*>(sp);
                const float4 v1 = *reinterpret_cast<const float4*>(sp + 4);
                uint32_t r0, r1, r2, r3;
                if (!lo) {
                    r0 = hi2(v0.x, v0.y); r1 = hi2(v0.z, v0.w);
                    r2 = hi2(v1.x, v1.y); r3 = hi2(v1.z, v1.w);
                } else {
                    r0 = lo2(v0.x, v0.y); r1 = lo2(v0.z, v0.w);
                    r2 = lo2(v1.x, v1.y); r3 = lo2(v1.z, v1.w);
                }
                sts128(sa + ld_off[w2], r0, r1, r2, r3);
            }
        } else {
#pragma unroll
            for (int w2 = 0; w2 < 4; ++w2)
                cp_async16(sa + ld_off[w2], Ag + (size_t)w2 * 32 * lda + kt);
        }
#pragma unroll
        for (int w2 = 0; w2 < 4; ++w2)
            cp_async16(sa + 16384u + ld_off[w2], Bg + (size_t)w2 * 32 * ldb + kt);
        cp_commit();
    };

    issue(0, 0);
    issue(1, 64);

    for (int i = 0; i < nst; ++i) {
        cp_wait1();
        __syncthreads();
        if (i + 2 < nst) issue((i + 2) % 3, (i + 2) * 64);
        else             cp_commit();

        const uint32_t sa = sb + (uint32_t)(i % 3) * 32768u;
        const uint32_t sB = sa + 16384u;
#pragma unroll
        for (int kk = 0; kk < 4; ++kk) {
            uint32_t a[4][4], b[2][4];
#pragma unroll
            for (int mt = 0; mt < 4; ++mt)
                ldsm4(a[mt], sa + aTerm[mt] + ((kk * 32 + aCol) ^ aXor[mt]));
#pragma unroll
            for (int nt = 0; nt < 2; ++nt)
                ldsm4(b[nt], sB + bTerm[nt] + ((kk * 32 + bCol) ^ bXor[nt]));
#pragma unroll
            for (int mt = 0; mt < 4; ++mt)
#pragma unroll
                for (int n8 = 0; n8 < 4; ++n8)
                    mma16816(acc[mt][n8], a[mt],
                             b[n8 >> 1][(n8 & 1) * 2], b[n8 >> 1][(n8 & 1) * 2 + 1]);
        }
        // no trailing sync (next iteration's sync orders stage reuse)
    }

    // ---- epilogue ----
    float bb[4][2];
#pragma unroll
    for (int n8 = 0; n8 < 4; ++n8) {
        if (g.bias) {
            const int col = n0 + wn * 32 + n8 * 8 + (lane & 3) * 2;
            bb[n8][0] = __ldg(&g.bias[col]);
            bb[n8][1] = __ldg(&g.bias[col + 1]);
        } else { bb[n8][0] = 0.0f; bb[n8][1] = 0.0f; }
    }

#pragma unroll
    for (int mt = 0; mt < 4; ++mt) {
#pragma unroll
        for (int half = 0; half < 2; ++half) {
            const int r = m0 + wm * 64 + mt * 16 + (lane >> 2) + half * 8;
#pragma unroll
            for (int n8 = 0; n8 < 4; ++n8) {
                const int col = n0 + wn * 32 + n8 * 8 + (lane & 3) * 2;
                float v0 = acc[mt][n8][half * 2 + 0] + bb[n8][0];
                float v1 = acc[mt][n8][half * 2 + 1] + bb[n8][1];
                if (g.relu) { v0 = fmaxf(v0, 0.0f); v1 = fmaxf(v1, 0.0f); }
                if (g.mode == 0) {
                    *reinterpret_cast<float2*>(g.C + (size_t)r * g.ldc + col) = make_float2(v0, v1);
                } else {
                    __half2 h, l; split2h(v0, v1, h, l);
                    __half* Sr = g.S + (size_t)r * (3 * g.Nfull) + col;
                    *reinterpret_cast<__half2*>(Sr)           = h;
                    *reinterpret_cast<__half2*>(Sr + g.Nfull) = l;
                }
            }
        }
    }
}

// ------- pack: fp32 [R,C] -> fp16 2-seg B-side split [hi|hi], 4 elems/thread -
__global__ __launch_bounds__(256)
void pack2b(const float* __restrict__ src, __half* __restrict__ dst,
            int logC, long total)
{
    const long i = ((long)blockIdx.x * 256 + threadIdx.x) * 4;
    if (i >= total) return;
    const int  C = 1 << logC;
    const long r = i >> logC;
    const int  c = (int)(i & (C - 1));
    const float4 v = *reinterpret_cast<const float4*>(src + i);
    const uint2 H = make_uint2(hi2(v.x, v.y), hi2(v.z, v.w));
    __half* d = dst + r * (3L * C) + c;
    *reinterpret_cast<uint2*>(d)     = H;
    *reinterpret_cast<uint2*>(d + C) = H;
}

// ------- packGBm: G,Bm -> gacat/bacat/gpacat A-side 2-seg [hi|lo] ------------
__global__ __launch_bounds__(256)
void packGBm(const float* __restrict__ G, const float* __restrict__ Bm,
             __half* __restrict__ ga, __half* __restrict__ ba,
             __half* __restrict__ gpa)
{
    const long i = ((long)blockIdx.x * 256 + threadIdx.x) * 4;   // [0, 2048*2048)
    const long r = i >> 11;
    const int  c = (int)(i & 2047);
    const float4 gv = *reinterpret_cast<const float4*>(G + i);
    const float4 bv = *reinterpret_cast<const float4*>(Bm + i);
    const long base = r * 6144 + c;
    *reinterpret_cast<uint2*>(ga + base)         = make_uint2(hi2(gv.x, gv.y), hi2(gv.z, gv.w));
    *reinterpret_cast<uint2*>(ga + base + 2048)  = make_uint2(lo2(gv.x, gv.y), lo2(gv.z, gv.w));
    *reinterpret_cast<uint2*>(ba + base)         = make_uint2(hi2(bv.x, bv.y), hi2(bv.z, bv.w));
    *reinterpret_cast<uint2*>(ba + base + 2048)  = make_uint2(lo2(bv.x, bv.y), lo2(bv.z, bv.w));
    const float s0 = gv.x + bv.x, s1 = gv.y + bv.y, s2 = gv.z + bv.z, s3 = gv.w + bv.w;
    *reinterpret_cast<uint2*>(gpa + base)        = make_uint2(hi2(s0, s1), hi2(s2, s3));
    *reinterpret_cast<uint2*>(gpa + base + 2048) = make_uint2(lo2(s0, s1), lo2(s2, s3));
}

// ------- packh2: W_p,W_q -> plain fp16, one launch ---------------------------
__global__ __launch_bounds__(256)
void packh2(const float* __restrict__ s0, const float* __restrict__ s1,
            __half* __restrict__ d0, __half* __restrict__ d1, long total)
{
    const long i = ((long)blockIdx.x * 256 + threadIdx.x) * 4;
    if (i >= total) return;
    const float* s = blockIdx.y ? s1 : s0;
    __half*      d = blockIdx.y ? d1 : d0;
    const float4 v = *reinterpret_cast<const float4*>(s + i);
    *reinterpret_cast<uint2*>(d + i) = make_uint2(hi2(v.x, v.y), hi2(v.z, v.w));
}

// ------- wrepack: Wre = m1-m2, Wim = m3-m1-m2 -> B-side 2-seg [4096, 3072] ---
__global__ __launch_bounds__(256)
void wrepack(const float* __restrict__ wg, __half* __restrict__ dst)
{
    const long i = ((long)blockIdx.x * 256 + threadIdx.x) * 4;   // [0, 2048*1024)
    const long r = i >> 10;
    const int  c = (int)(i & 1023);
    const float4 m1 = *reinterpret_cast<const float4*>(wg + i);
    const float4 m2 = *reinterpret_cast<const float4*>(wg + 2048L * 1024 + i);
    const float4 m3 = *reinterpret_cast<const float4*>(wg + 2L * 2048 * 1024 + i);
    const float re[4] = {m1.x - m2.x, m1.y - m2.y, m1.z - m2.z, m1.w - m2.w};
    const float im[4] = {m3.x - m1.x - m2.x, m3.y - m1.y - m2.y,
                         m3.z - m1.z - m2.z, m3.w - m1.w - m2.w};
    {
        const uint2 H = make_uint2(hi2(re[0], re[1]), hi2(re[2], re[3]));
        __half* d = dst + r * 3072 + c;
        *reinterpret_cast<uint2*>(d)        = H;
        *reinterpret_cast<uint2*>(d + 1024) = H;
    }
    {
        const uint2 H = make_uint2(hi2(im[0], im[1]), hi2(im[2], im[3]));
        __half* d = dst + (2048 + r) * 3072 + c;
        *reinterpret_cast<uint2*>(d)        = H;
        *reinterpret_cast<uint2*>(d + 1024) = H;
    }
}

// ------- transpack: W_y halves -> transposed B-side 2-seg split ---------------
__global__ __launch_bounds__(256)
void transpack(const float* __restrict__ Wy, __half* __restrict__ dst)
{
    __shared__ float tile[32][33];
    const int z  = blockIdx.z;
    const int j0 = blockIdx.x * 32;
    const int k0 = blockIdx.y * 32;
    const int tx = threadIdx.x & 31, ty = threadIdx.x >> 5;

#pragma unroll
    for (int rr = ty; rr < 32; rr += 8) {
        const int k = k0 + rr, j = j0 + tx;
        float v;
        if (z == 0)      v = Wy[(size_t)k * 1024 + j];
        else if (z == 1) v = Wy[(size_t)(k + 2048) * 1024 + j];
        else             v = Wy[(size_t)k * 1024 + j] + Wy[(size_t)(k + 2048) * 1024 + j];
        tile[rr][tx] = v;
    }
    __syncthreads();
#pragma unroll
    for (int rr = ty; rr < 32; rr += 8) {
        const int j = j0 + rr;
        const float v = tile[tx][rr];
        const __half h = __float2half_rn(v);
        __half* d = dst + (size_t)z * 1024 * 6144 + (size_t)j * 6144 + k0 + tx;
        d[0] = h; d[2048] = h;
    }
}

// ------- biasdot -> [bre | bim] ------------------------------------------------
__global__ __launch_bounds__(256)
void biasdot(const float* __restrict__ G, const float* __restrict__ Bm,
             const float* __restrict__ b_y, float* __restrict__ breim)
{
    const int c = blockIdx.x, tid = threadIdx.x, lane = tid & 31, w = tid >> 5;
    float s1 = 0, s2 = 0, s3 = 0;
    for (int k = tid; k < 2048; k += 256) {
        const float g = G[(size_t)c * 2048 + k], bm = Bm[(size_t)c * 2048 + k];
        const float byu = b_y[k], byw = b_y[2048 + k];
        s1 += g * byu; s2 += bm * byw; s3 += (g + bm) * (byu + byw);
    }
#pragma unroll
    for (int o = 16; o; o >>= 1) {
        s1 += __shfl_down_sync(0xFFFFFFFFu, s1, o);
        s2 += __shfl_down_sync(0xFFFFFFFFu, s2, o);
        s3 += __shfl_down_sync(0xFFFFFFFFu, s3, o);
    }
    __shared__ float sh[3][8];
    if (lane == 0) { sh[0][w] = s1; sh[1][w] = s2; sh[2][w] = s3; }
    __syncthreads();
    if (tid == 0) {
        float a = 0, b = 0, d = 0;
#pragma unroll
        for (int i = 0; i < 8; ++i) { a += sh[0][i]; b += sh[1][i]; d += sh[2][i]; }
        breim[c] = a - b;
        breim[2048 + c] = d - a - b;
    }
}

// ---------------- polar combine -> plain fp16 pp/qp ---------------------------
__global__ __launch_bounds__(256)
void combine(const float* __restrict__ uw, const float* __restrict__ t,
             const float* __restrict__ bias_p, const float* __restrict__ bias_q,
             __half* __restrict__ pph, __half* __restrict__ qph)
{
    const long i = ((long)blockIdx.x * 256 + threadIdx.x) * 4;   // [0, 8192*2048)
    const long r = i >> 11;
    const int  c = (int)(i & 2047);
    const float4 u4 = *reinterpret_cast<const float4*>(uw + r * 4096 + c);
    const float4 w4 = *reinterpret_cast<const float4*>(uw + r * 4096 + 2048 + c);
    const float4 re = *reinterpret_cast<const float4*>(t + r * 4096 + c);
    const float4 im = *reinterpret_cast<const float4*>(t + r * 4096 + 2048 + c);
    const float4 bp = *reinterpret_cast<const float4*>(bias_p + c);
    const float4 bq = *reinterpret_cast<const float4*>(bias_q + c);

    float pv[4], qv[4];
    const float uu[4] = {u4.x, u4.y, u4.z, u4.w};
    const float ww[4] = {w4.x, w4.y, w4.z, w4.w};
    const float rr[4] = {re.x, re.y, re.z, re.w};
    const float ii[4] = {im.x, im.y, im.z, im.w};
    const float bpv[4] = {bp.x, bp.y, bp.z, bp.w};
    const float bqv[4] = {bq.x, bq.y, bq.z, bq.w};
#pragma unroll
    for (int j = 0; j < 4; ++j) {
        pv[j] = uu[j] * rr[j] + ww[j] * ii[j] + bpv[j];
        qv[j] = ww[j] * rr[j] - uu[j] * ii[j] + bqv[j];
    }
    *reinterpret_cast<uint2*>(pph + i) =
        make_uint2(hi2(pv[0], pv[1]), hi2(pv[2], pv[3]));
    *reinterpret_cast<uint2*>(qph + i) =
        make_uint2(hi2(qv[0], qv[1]), hi2(qv[2], qv[3]));
}

// ---------------- host side --------------------------------------------------
extern "C" void kernel_launch(void* const* d_in, const int* in_sizes, int n_in,
                              void* d_out, int out_size)
{
    const float* x      = (const float*)d_in[0];
    const float* W_h    = (const float*)d_in[1];
    const float* b_h    = (const float*)d_in[2];
    const float* W_h2   = (const float*)d_in[3];
    const float* b_h2   = (const float*)d_in[4];
    const float* W_y    = (const float*)d_in[5];
    const float* b_y    = (const float*)d_in[6];
    const float* G      = (const float*)d_in[7];
    const float* Bm     = (const float*)d_in[8];
    const float* bias_p = (const float*)d_in[9];
    const float* bias_q = (const float*)d_in[10];
    const float* W_p    = (const float*)d_in[11];
    const float* b_p    = (const float*)d_in[12];
    const float* W_q    = (const float*)d_in[13];
    const float* b_q    = (const float*)d_in[14];

    float* out = (float*)d_out;
    float* uw  = out;
    float* p   = out + (size_t)8192 * 4096;
    float* q   = p   + (size_t)8192 * 2048;

    __half *whcat, *h1cat, *wh2cat, *h2cat, *wycat,
           *gacat, *bacat, *gpacat, *wytcat, *wreim,
           *pph, *qph, *wph, *wqh;
    float *t, *wg, *breim;
    cudaGetSymbolAddress((void**)&whcat, g_whcat);
    cudaGetSymbolAddress((void**)&h1cat, g_h1cat);
    cudaGetSymbolAddress((void**)&wh2cat,g_wh2cat);
    cudaGetSymbolAddress((void**)&h2cat, g_h2cat);
    cudaGetSymbolAddress((void**)&wycat, g_wycat);
    cudaGetSymbolAddress((void**)&gacat, g_gacat);
    cudaGetSymbolAddress((void**)&bacat, g_bacat);
    cudaGetSymbolAddress((void**)&gpacat,g_gpacat);
    cudaGetSymbolAddress((void**)&wytcat,g_wytcat);
    cudaGetSymbolAddress((void**)&wg,    g_wg);
    cudaGetSymbolAddress((void**)&wreim, g_wreim);
    cudaGetSymbolAddress((void**)&breim, g_breim);
    cudaGetSymbolAddress((void**)&t,     g_t);
    cudaGetSymbolAddress((void**)&pph,   g_pph);
    cudaGetSymbolAddress((void**)&qph,   g_qph);
    cudaGetSymbolAddress((void**)&wph,   g_wph);
    cudaGetSymbolAddress((void**)&wqh,   g_wqh);

    cudaFuncSetAttribute(gemm_mma, cudaFuncAttributeMaxDynamicSharedMemorySize, SMEM_BYTES);

    // ---- packs (x is consumed fp32-direct by G1; no xcat pack) ----
    pack2b<<<(1024L * 4096 / 4 + 255) / 256, 256>>>(W_h,  whcat,  12, 1024L * 4096);
    pack2b<<<(1024L * 1024 / 4 + 255) / 256, 256>>>(W_h2, wh2cat, 10, 1024L * 1024);
    pack2b<<<(4096L * 1024 / 4 + 255) / 256, 256>>>(W_y,  wycat,  10, 4096L * 1024);
    packGBm<<<(2048L * 2048 / 4 + 255) / 256, 256>>>(G, Bm, gacat, bacat, gpacat);
    transpack<<<dim3(32, 64, 3), 256>>>(W_y, wytcat);
    biasdot<<<2048, 256>>>(G, Bm, b_y, breim);
    packh2<<<dim3((2048L * 2048 / 4 + 255) / 256, 2), 256>>>(W_p, W_q, wph, wqh, 2048L * 2048);

    const dim3 blk(256);
    // FUSED: z=0 G1 (fp32-direct x, M=8192,N=1024,K'=8192, relu -> split h1cat)
    //        z=1..3 compositions (M=2048,N=1024,K'=4096 -> fp32 wg)
    {
        GemmArgs a0{nullptr, whcat,                 b_h,     nullptr, h1cat, x,
                    4096,  12288, 0,    1024, 8192, 64, 1, 1};
        GemmArgs a1{gacat,  wytcat,                nullptr, wg,                    nullptr, nullptr,
                    6144,  6144,  1024, 0,    4096, 16, 0, 0};
        GemmArgs a2{bacat,  wytcat + 1024L * 6144, nullptr, wg + 2048L * 1024,     nullptr, nullptr,
                    6144,  6144,  1024, 0,    4096, 16, 0, 0};
        GemmArgs a3{gpacat, wytcat + 2048L * 6144, nullptr, wg + 2L * 2048 * 1024, nullptr, nullptr,
                    6144,  6144,  1024, 0,    4096, 16, 0, 0};
        gemm_mma<<<dim3(8, 64, 4), blk, SMEM_BYTES>>>(a0, a1, a2, a3);
    }
    // Weight-level Karatsuba: Wre = m1-m2, Wim = m3-m1-m2 -> 2-seg B-side pack
    wrepack<<<(2048L * 1024 / 4 + 255) / 256, 256>>>(wg, wreim);

    // G2: h2 = relu(h1 @ W_h2^T + b_h2) -> 2-seg split h2cat.  K'=2048.
    {
        GemmArgs a{h1cat, wh2cat, b_h2, nullptr, h2cat, nullptr,
                   3072, 3072, 0, 1024, 2048, 64, 1, 1};
        gemm_mma<<<dim3(8, 64, 1), blk, SMEM_BYTES>>>(a, a, a, a);
    }
    // G3 + mixing (z=2), both [8192,4096], K'=2048
    {
        GemmArgs a0{h2cat, wycat, b_y,   uw, nullptr, nullptr, 3072, 3072, 4096, 0, 2048, 64, 0, 0};
        GemmArgs a1{h2cat, wreim, breim, t,  nullptr, nullptr, 3072, 3072, 4096, 0, 2048, 64, 0, 0};
        gemm_mma<<<dim3(32, 64, 2), blk, SMEM_BYTES>>>(a0, a1, a0, a0);
    }
    // combine -> plain fp16 pp/qp
    combine<<<(8192L * 2048 / 4) / 256, 256>>>(uw, t, bias_p, bias_q, pph, qph);
    // G5/G6: final projections, plain fp16, K=2048
    {
        GemmArgs a0{pph, wph, b_p, p, nullptr, nullptr, 2048, 2048, 2048, 0, 2048, 64, 0, 0};
        GemmArgs a1{qph, wqh, b_q, q, nullptr, nullptr, 2048, 2048, 2048, 0, 2048, 64, 0, 0};
        gemm_mma<<<dim3(16, 64, 2), blk, SMEM_BYTES>>>(a0, a1, a0, a0);
    }
}